// round 3
// baseline (speedup 1.0000x reference)
#include <cuda_runtime.h>

// FFTLayer: out = Re(FFT_512(x * win)) for 65536 rows of 512 fp32.
// Strategy: pack 2 real rows into one complex FFT (z = a + i*b), then
// 512 = 8*8*8 radix-8 FFT with 64 threads/FFT, 8 complex values in
// registers per thread, two padded shared-memory transposes.

#define NFFT       512
#define U_THREADS  64     // threads per FFT unit
#define UNITS      4      // FFT units per block
#define THREADS    (U_THREADS * UNITS)
#define EX_STRIDE  72     // padded row stride for exchanges (conflict avoidance)
#define EX_SIZE    (8 * EX_STRIDE)

__device__ __forceinline__ float2 cadd(float2 a, float2 b) { return make_float2(a.x + b.x, a.y + b.y); }
__device__ __forceinline__ float2 csub(float2 a, float2 b) { return make_float2(a.x - b.x, a.y - b.y); }
__device__ __forceinline__ float2 cmul(float2 a, float2 b) {
    return make_float2(a.x * b.x - a.y * b.y, a.x * b.y + a.y * b.x);
}
// multiply by -i  (W4^1 = e^{-i pi/2})
__device__ __forceinline__ float2 mnegi(float2 a) { return make_float2(a.y, -a.x); }

// In-place 8-point DIF FFT: v[r] <- sum_i v_in[i] * W8^{r*i},  W8 = e^{-2*pi*i/8}
__device__ __forceinline__ void fft8(float2 v[8]) {
    const float C = 0.70710678118654752440f;  // sqrt(2)/2
    float2 a0 = cadd(v[0], v[4]), a4 = csub(v[0], v[4]);
    float2 a1 = cadd(v[1], v[5]), a5 = csub(v[1], v[5]);
    float2 a2 = cadd(v[2], v[6]), a6 = csub(v[2], v[6]);
    float2 a3 = cadd(v[3], v[7]), a7 = csub(v[3], v[7]);
    // a5 *= (C, -C) ; a6 *= -i ; a7 *= (-C, -C)
    a5 = make_float2(C * (a5.x + a5.y), C * (a5.y - a5.x));
    a6 = mnegi(a6);
    a7 = make_float2(C * (a7.y - a7.x), -C * (a7.x + a7.y));
    float2 b0 = cadd(a0, a2), b2 = csub(a0, a2);
    float2 b1 = cadd(a1, a3), b3 = mnegi(csub(a1, a3));
    float2 b4 = cadd(a4, a6), b6 = csub(a4, a6);
    float2 b5 = cadd(a5, a7), b7 = mnegi(csub(a5, a7));
    v[0] = cadd(b0, b1); v[4] = csub(b0, b1);
    v[2] = cadd(b2, b3); v[6] = csub(b2, b3);
    v[1] = cadd(b4, b5); v[5] = csub(b4, b5);
    v[3] = cadd(b6, b7); v[7] = csub(b6, b7);
}

// Apply v[r] *= w1^r for r = 1..7 (chained powers; 1 ulp-ish growth, fine for fp32)
__device__ __forceinline__ void twiddle7(float2 v[8], float2 w1) {
    float2 wp = w1;
#pragma unroll
    for (int r = 1; r < 8; r++) {
        v[r] = cmul(v[r], wp);
        if (r < 7) wp = cmul(wp, w1);
    }
}

__global__ void __launch_bounds__(THREADS, 8)
fft512_real_kernel(const float* __restrict__ x,
                   const float* __restrict__ win,
                   float* __restrict__ out,
                   int n_pairs) {
    __shared__ float s_re[UNITS][EX_SIZE];
    __shared__ float s_im[UNITS][EX_SIZE];

    const int tid  = threadIdx.x;
    const int unit = tid >> 6;        // FFT unit within block
    const int u    = tid & 63;        // lane within FFT unit (0..63)
    const int pair = blockIdx.x * UNITS + unit;
    if (pair >= n_pairs) return;      // (grid divides exactly here, but be safe)

    const float* xa = x + (size_t)pair * 2 * NFFT;  // row a (real part)
    const float* xb = xa + NFFT;                    // row b (imag part)
    float* oa = out + (size_t)pair * 2 * NFFT;
    float* ob = oa + NFFT;

    float* re = s_re[unit];
    float* im = s_im[unit];

    float2 v[8];

    // ---- Pass 1: load + window, FFT8 over i (elements u + 64*i), twiddle W512^{u*r}
#pragma unroll
    for (int i = 0; i < 8; i++) {
        const int idx = u + 64 * i;
        const float w = __ldg(&win[idx]);
        v[i].x = xa[idx] * w;
        v[i].y = xb[idx] * w;
    }
    fft8(v);
    {
        float s, c;
        sincospif(-(float)u * (1.0f / 256.0f), &s, &c);  // e^{-2 pi i u / 512}
        twiddle7(v, make_float2(c, s));
    }
    // exchange 1: y_r[q=u] at [72*r + u]   (writes & reads conflict-free)
#pragma unroll
    for (int r = 0; r < 8; r++) {
        re[EX_STRIDE * r + u] = v[r].x;
        im[EX_STRIDE * r + u] = v[r].y;
    }
    __syncthreads();

    // ---- Pass 2: thread = (r, q1). FFT8 over q2 (gather stride 8), twiddle W64^{q1*r2}
    const int r  = u >> 3;
    const int q1 = u & 7;
#pragma unroll
    for (int q2 = 0; q2 < 8; q2++) {
        const int a = EX_STRIDE * r + q1 + 8 * q2;
        v[q2] = make_float2(re[a], im[a]);
    }
    fft8(v);
    {
        float s, c;
        sincospif(-(float)q1 * (1.0f / 32.0f), &s, &c);  // e^{-2 pi i q1 / 64}
        twiddle7(v, make_float2(c, s));
    }
    __syncthreads();  // all exchange-1 reads done before overwrite
    // exchange 2: z_{r,r2}[q1] at [72*r + 8*r2 + q1]
#pragma unroll
    for (int r2 = 0; r2 < 8; r2++) {
        const int a = EX_STRIDE * r + 8 * r2 + q1;
        re[a] = v[r2].x;
        im[a] = v[r2].y;
    }
    __syncthreads();

    // ---- Pass 3: thread = (r, r2). FFT8 over q1 (contiguous gather). No twiddle.
    const int r2 = u & 7;
#pragma unroll
    for (int q1b = 0; q1b < 8; q1b++) {
        const int a = EX_STRIDE * r + 8 * r2 + q1b;
        v[q1b] = make_float2(re[a], im[a]);
    }
    fft8(v);
    __syncthreads();  // exchange-2 reads done before final-store reuse

    // final natural-order store: X[64*k2 + 8*r2 + r]
#pragma unroll
    for (int k2 = 0; k2 < 8; k2++) {
        const int k = 64 * k2 + 8 * r2 + r;
        re[k] = v[k2].x;
        im[k] = v[k2].y;
    }
    __syncthreads();

    // ---- Epilogue: unpack two real spectra.
    // Re A[k] = (Re Z[k] + Re Z[(512-k)&511]) / 2
    // Re B[k] = (Im Z[k] + Im Z[(512-k)&511]) / 2
#pragma unroll
    for (int jj = 0; jj < 8; jj++) {
        const int k  = u + 64 * jj;
        const int kk = (NFFT - k) & (NFFT - 1);
        oa[k] = 0.5f * (re[k] + re[kk]);
        ob[k] = 0.5f * (im[k] + im[kk]);
    }
}

extern "C" void kernel_launch(void* const* d_in, const int* in_sizes, int n_in,
                              void* d_out, int out_size) {
    const float* x   = (const float*)d_in[0];   // (256, 256, 512) fp32
    const float* win = (const float*)d_in[1];   // (512,) fp32
    float* out = (float*)d_out;                 // (256, 256, 512, 1) fp32

    const int n_rows  = in_sizes[0] / NFFT;     // 65536
    const int n_pairs = n_rows / 2;             // 32768
    const int blocks  = (n_pairs + UNITS - 1) / UNITS;  // 8192

    fft512_real_kernel<<<blocks, THREADS>>>(x, win, out, n_pairs);
}

// round 4
// speedup vs baseline: 1.1816x; 1.1816x over previous
#include <cuda_runtime.h>

// FFTLayer: out = Re(FFT_512(x * win)) for 65536 rows of 512 fp32.
// Pack 2 real rows into one complex FFT (z = a + i*b); 512 = 8*8*8 radix-8,
// 64 threads/FFT, 8 complex values in registers, conflict-free padded smem
// exchanges (R3 fix: pass-3 gather was 8-way bank conflicted).

#define NFFT       512
#define U_THREADS  64
#define UNITS      4
#define THREADS    (U_THREADS * UNITS)
#define EX_SIZE    576   // >= 72*7 + 9*7 + 7 = 574 and >= 65*7 + 63 = 518

// per-unit barrier: both warps of the unit, named barrier id unit+1
#define UNIT_BAR() asm volatile("bar.sync %0, 64;" :: "r"(unit + 1) : "memory")

__device__ __forceinline__ float2 cadd(float2 a, float2 b) { return make_float2(a.x + b.x, a.y + b.y); }
__device__ __forceinline__ float2 csub(float2 a, float2 b) { return make_float2(a.x - b.x, a.y - b.y); }
__device__ __forceinline__ float2 cmul(float2 a, float2 b) {
    return make_float2(a.x * b.x - a.y * b.y, a.x * b.y + a.y * b.x);
}
__device__ __forceinline__ float2 mnegi(float2 a) { return make_float2(a.y, -a.x); }

// In-place 8-point DIF FFT: v[r] <- sum_i v_in[i] * W8^{r*i},  W8 = e^{-2*pi*i/8}
__device__ __forceinline__ void fft8(float2 v[8]) {
    const float C = 0.70710678118654752440f;
    float2 a0 = cadd(v[0], v[4]), a4 = csub(v[0], v[4]);
    float2 a1 = cadd(v[1], v[5]), a5 = csub(v[1], v[5]);
    float2 a2 = cadd(v[2], v[6]), a6 = csub(v[2], v[6]);
    float2 a3 = cadd(v[3], v[7]), a7 = csub(v[3], v[7]);
    a5 = make_float2(C * (a5.x + a5.y), C * (a5.y - a5.x));
    a6 = mnegi(a6);
    a7 = make_float2(C * (a7.y - a7.x), -C * (a7.x + a7.y));
    float2 b0 = cadd(a0, a2), b2 = csub(a0, a2);
    float2 b1 = cadd(a1, a3), b3 = mnegi(csub(a1, a3));
    float2 b4 = cadd(a4, a6), b6 = csub(a4, a6);
    float2 b5 = cadd(a5, a7), b7 = mnegi(csub(a5, a7));
    v[0] = cadd(b0, b1); v[4] = csub(b0, b1);
    v[2] = cadd(b2, b3); v[6] = csub(b2, b3);
    v[1] = cadd(b4, b5); v[5] = csub(b4, b5);
    v[3] = cadd(b6, b7); v[7] = csub(b6, b7);
}

__device__ __forceinline__ void twiddle7(float2 v[8], float2 w1) {
    float2 wp = w1;
#pragma unroll
    for (int r = 1; r < 8; r++) {
        v[r] = cmul(v[r], wp);
        if (r < 7) wp = cmul(wp, w1);
    }
}

__global__ void __launch_bounds__(THREADS, 8)
fft512_real_kernel(const float* __restrict__ x,
                   const float* __restrict__ win,
                   float* __restrict__ out,
                   int n_pairs) {
    __shared__ float s_re[UNITS][EX_SIZE];
    __shared__ float s_im[UNITS][EX_SIZE];

    const int tid  = threadIdx.x;
    const int unit = tid >> 6;
    const int u    = tid & 63;
    const int pair = blockIdx.x * UNITS + unit;
    if (pair >= n_pairs) return;

    const float* xa = x + (size_t)pair * 2 * NFFT;
    const float* xb = xa + NFFT;
    float* oa = out + (size_t)pair * 2 * NFFT;
    float* ob = oa + NFFT;

    float* re = s_re[unit];
    float* im = s_im[unit];

    float2 v[8];

    // ---- Pass 1: load + window, FFT8 over i (elements u + 64*i), twiddle W512^{u*r}
#pragma unroll
    for (int i = 0; i < 8; i++) {
        const int idx = u + 64 * i;
        const float w = __ldg(&win[idx]);
        v[i].x = xa[idx] * w;
        v[i].y = xb[idx] * w;
    }
    fft8(v);
    {
        float s, c;
        sincospif(-(float)u * (1.0f / 256.0f), &s, &c);  // e^{-2 pi i u / 512}
        twiddle7(v, make_float2(c, s));
    }
    // exchange 1: y_r[q=u] at [72*r + u]  (write lanes u: conflict-free)
#pragma unroll
    for (int r = 0; r < 8; r++) {
        re[72 * r + u] = v[r].x;
        im[72 * r + u] = v[r].y;
    }
    UNIT_BAR();

    // ---- Pass 2: thread = (r, q1). Gather over q2 (addr = 72r + q1 + 8q2: banks
    // 8r+q1+8q2 distinct per lane -> conflict-free). FFT8, twiddle W64^{q1*r2}.
    const int r  = u >> 3;
    const int q1 = u & 7;
#pragma unroll
    for (int q2 = 0; q2 < 8; q2++) {
        const int a = 72 * r + q1 + 8 * q2;
        v[q2] = make_float2(re[a], im[a]);
    }
    fft8(v);
    {
        float s, c;
        sincospif(-(float)q1 * (1.0f / 32.0f), &s, &c);  // e^{-2 pi i q1 / 64}
        twiddle7(v, make_float2(c, s));
    }
    UNIT_BAR();  // all exchange-1 reads done before overwrite
    // exchange 2: z_{r,r2}[q1] at [72*r + 9*r2 + q1]
    // write lanes (r,q1): banks 8r+9r2+q1, r2 fixed -> 8r+q1 spans 0..31: CF
#pragma unroll
    for (int r2 = 0; r2 < 8; r2++) {
        const int a = 72 * r + 9 * r2 + q1;
        re[a] = v[r2].x;
        im[a] = v[r2].y;
    }
    UNIT_BAR();

    // ---- Pass 3: thread = (r, r2). Gather over q1 (addr = 72r + 9r2 + q1:
    // banks 8r+9r2 injective mod 32 over lanes -> conflict-free). FFT8, no twiddle.
    const int r2 = u & 7;
#pragma unroll
    for (int q1b = 0; q1b < 8; q1b++) {
        const int a = 72 * r + 9 * r2 + q1b;
        v[q1b] = make_float2(re[a], im[a]);
    }
    fft8(v);
    UNIT_BAR();  // exchange-2 reads done before final-store reuse

    // final store, padded natural order: X[k] at addr 65*(k>>6) + (k&63)
    // k = 64*k2 + 8*r2 + r  ->  addr = 65*k2 + 8*r2 + r
#pragma unroll
    for (int k2 = 0; k2 < 8; k2++) {
        const int a = 65 * k2 + 8 * r2 + r;
        re[a] = v[k2].x;
        im[a] = v[k2].y;
    }
    UNIT_BAR();

    // ---- Epilogue: unpack two real spectra.
    // Re A[k] = (Re Z[k] + Re Z[(512-k)&511]) / 2
    // Re B[k] = (Im Z[k] + Im Z[(512-k)&511]) / 2
#pragma unroll
    for (int jj = 0; jj < 8; jj++) {
        const int k  = u + 64 * jj;
        const int kk = (NFFT - k) & (NFFT - 1);
        const int ak  = 65 * jj + u;                    // 65*(k>>6) + (k&63)
        const int akk = 65 * (kk >> 6) + (kk & 63);
        oa[k] = 0.5f * (re[ak] + re[akk]);
        ob[k] = 0.5f * (im[ak] + im[akk]);
    }
}

extern "C" void kernel_launch(void* const* d_in, const int* in_sizes, int n_in,
                              void* d_out, int out_size) {
    const float* x   = (const float*)d_in[0];   // (256, 256, 512) fp32
    const float* win = (const float*)d_in[1];   // (512,) fp32
    float* out = (float*)d_out;                 // (256, 256, 512, 1) fp32

    const int n_rows  = in_sizes[0] / NFFT;     // 65536
    const int n_pairs = n_rows / 2;             // 32768
    const int blocks  = (n_pairs + UNITS - 1) / UNITS;

    fft512_real_kernel<<<blocks, THREADS>>>(x, win, out, n_pairs);
}

// round 5
// speedup vs baseline: 1.3953x; 1.1809x over previous
#include <cuda_runtime.h>

// FFTLayer: out = Re(FFT_512(x * win)) for 65536 rows of 512 fp32.
// Pack 2 real rows into one complex FFT (z = a + i*b); 512 = 8*8*8 radix-8,
// 64 threads per CTA = one FFT, 8 complex values in registers, conflict-free
// padded smem exchanges. R4 fix: named barriers capped occupancy at ~44%
// (SM barrier pool); one-unit CTAs + __syncthreads restore full occupancy.

#define NFFT     512
#define THREADS  64
#define EX_SIZE  576   // >= 72*7 + 9*7 + 7 = 574 and >= 65*7 + 63 = 518

__device__ __forceinline__ float2 cadd(float2 a, float2 b) { return make_float2(a.x + b.x, a.y + b.y); }
__device__ __forceinline__ float2 csub(float2 a, float2 b) { return make_float2(a.x - b.x, a.y - b.y); }
__device__ __forceinline__ float2 cmul(float2 a, float2 b) {
    return make_float2(a.x * b.x - a.y * b.y, a.x * b.y + a.y * b.x);
}
__device__ __forceinline__ float2 mnegi(float2 a) { return make_float2(a.y, -a.x); }

// In-place 8-point DIF FFT: v[r] <- sum_i v_in[i] * W8^{r*i},  W8 = e^{-2*pi*i/8}
__device__ __forceinline__ void fft8(float2 v[8]) {
    const float C = 0.70710678118654752440f;
    float2 a0 = cadd(v[0], v[4]), a4 = csub(v[0], v[4]);
    float2 a1 = cadd(v[1], v[5]), a5 = csub(v[1], v[5]);
    float2 a2 = cadd(v[2], v[6]), a6 = csub(v[2], v[6]);
    float2 a3 = cadd(v[3], v[7]), a7 = csub(v[3], v[7]);
    a5 = make_float2(C * (a5.x + a5.y), C * (a5.y - a5.x));
    a6 = mnegi(a6);
    a7 = make_float2(C * (a7.y - a7.x), -C * (a7.x + a7.y));
    float2 b0 = cadd(a0, a2), b2 = csub(a0, a2);
    float2 b1 = cadd(a1, a3), b3 = mnegi(csub(a1, a3));
    float2 b4 = cadd(a4, a6), b6 = csub(a4, a6);
    float2 b5 = cadd(a5, a7), b7 = mnegi(csub(a5, a7));
    v[0] = cadd(b0, b1); v[4] = csub(b0, b1);
    v[2] = cadd(b2, b3); v[6] = csub(b2, b3);
    v[1] = cadd(b4, b5); v[5] = csub(b4, b5);
    v[3] = cadd(b6, b7); v[7] = csub(b6, b7);
}

__device__ __forceinline__ void twiddle7(float2 v[8], float2 w1) {
    float2 wp = w1;
#pragma unroll
    for (int r = 1; r < 8; r++) {
        v[r] = cmul(v[r], wp);
        if (r < 7) wp = cmul(wp, w1);
    }
}

__global__ void __launch_bounds__(THREADS, 32)
fft512_real_kernel(const float* __restrict__ x,
                   const float* __restrict__ win,
                   float* __restrict__ out) {
    __shared__ float re[EX_SIZE];
    __shared__ float im[EX_SIZE];

    const int u    = threadIdx.x;     // 0..63
    const int pair = blockIdx.x;

    const float* xa = x + (size_t)pair * 2 * NFFT;
    const float* xb = xa + NFFT;
    float* oa = out + (size_t)pair * 2 * NFFT;
    float* ob = oa + NFFT;

    float2 v[8];

    // ---- Pass 1: load + window (0.5x folded in for the unpack), FFT8 over
    // elements u + 64*i, twiddle W512^{u*r}
#pragma unroll
    for (int i = 0; i < 8; i++) {
        const int idx = u + 64 * i;
        const float w = 0.5f * __ldg(&win[idx]);
        v[i].x = xa[idx] * w;
        v[i].y = xb[idx] * w;
    }
    fft8(v);
    {
        float s, c;
        sincospif(-(float)u * (1.0f / 256.0f), &s, &c);  // e^{-2 pi i u / 512}
        twiddle7(v, make_float2(c, s));
    }
    // exchange 1: y_r[q=u] at [72*r + u]  (write lanes u consecutive: CF)
#pragma unroll
    for (int r = 0; r < 8; r++) {
        re[72 * r + u] = v[r].x;
        im[72 * r + u] = v[r].y;
    }
    __syncthreads();

    // ---- Pass 2: thread = (r, q1). Gather stride 8 (banks 8r+q1+8q2 distinct
    // per lane: CF). FFT8, twiddle W64^{q1*r2}.
    const int r  = u >> 3;
    const int q1 = u & 7;
#pragma unroll
    for (int q2 = 0; q2 < 8; q2++) {
        const int a = 72 * r + q1 + 8 * q2;
        v[q2] = make_float2(re[a], im[a]);
    }
    fft8(v);
    {
        float s, c;
        sincospif(-(float)q1 * (1.0f / 32.0f), &s, &c);  // e^{-2 pi i q1 / 64}
        twiddle7(v, make_float2(c, s));
    }
    __syncthreads();  // all exchange-1 reads done before overwrite
    // exchange 2: z_{r,r2}[q1] at [72*r + 9*r2 + q1]
    // write lanes (r,q1): banks 8r+q1 span 0..31: CF
#pragma unroll
    for (int r2 = 0; r2 < 8; r2++) {
        const int a = 72 * r + 9 * r2 + q1;
        re[a] = v[r2].x;
        im[a] = v[r2].y;
    }
    __syncthreads();

    // ---- Pass 3: thread = (r, r2). Gather (banks 8r+9r2 injective mod 32: CF).
    // FFT8, no twiddle.
    const int r2 = u & 7;
#pragma unroll
    for (int q1b = 0; q1b < 8; q1b++) {
        const int a = 72 * r + 9 * r2 + q1b;
        v[q1b] = make_float2(re[a], im[a]);
    }
    fft8(v);
    __syncthreads();  // exchange-2 reads done before final-store reuse

    // final store, padded natural order: X[k] at addr 65*(k>>6) + (k&63)
    // k = 64*k2 + 8*r2 + r  ->  addr = 65*k2 + 8*r2 + r   (benign 2-way)
#pragma unroll
    for (int k2 = 0; k2 < 8; k2++) {
        const int a = 65 * k2 + 8 * r2 + r;
        re[a] = v[k2].x;
        im[a] = v[k2].y;
    }
    __syncthreads();

    // ---- Epilogue: unpack two real spectra (0.5 factor already in window).
    // Re A[k] = Re Z[k] + Re Z[(512-k)&511]
    // Re B[k] = Im Z[k] + Im Z[(512-k)&511]
#pragma unroll
    for (int jj = 0; jj < 8; jj++) {
        const int k  = u + 64 * jj;
        const int kk = (NFFT - k) & (NFFT - 1);
        const int ak  = 65 * jj + u;
        const int akk = 65 * (kk >> 6) + (kk & 63);
        oa[k] = re[ak] + re[akk];
        ob[k] = im[ak] + im[akk];
    }
}

extern "C" void kernel_launch(void* const* d_in, const int* in_sizes, int n_in,
                              void* d_out, int out_size) {
    const float* x   = (const float*)d_in[0];   // (256, 256, 512) fp32
    const float* win = (const float*)d_in[1];   // (512,) fp32
    float* out = (float*)d_out;                 // (256, 256, 512, 1) fp32

    const int n_rows  = in_sizes[0] / NFFT;     // 65536
    const int n_pairs = n_rows / 2;             // 32768

    fft512_real_kernel<<<n_pairs, THREADS>>>(x, win, out);
}